// round 1
// baseline (speedup 1.0000x reference)
#include <cuda_runtime.h>
#include <cuda_bf16.h>
#include <cstdint>

// Pairwise Euclidean distance: out[b,k] = sqrt(max(||x_b||^2 + ||c_k||^2 - 2 x_b.c_k, EPS))
// B=8192, K=256, D=3072, fp32 in/out.
// Cross-term via bf16 mma.sync (fp32 accum); norms in fp32 accumulated during tile loads.

#define BB 8192
#define KK 256
#define DD 3072
#define BM 128
#define BN 128
#define BK 32
#define NT (DD / BK)            // 96 k-tiles
#define LDS_STRIDE (BK + 8)     // 40 bf16 -> 80B row stride (conflict-free frag loads)
#define EPS_F 1e-12f

__global__ __launch_bounds__(256, 1)
void rbf_dist_kernel(const float* __restrict__ X,
                     const float* __restrict__ C,
                     float* __restrict__ out)
{
    __shared__ __align__(16) __nv_bfloat16 As[2][BM][LDS_STRIDE];
    __shared__ __align__(16) __nv_bfloat16 Bs[2][BN][LDS_STRIDE];
    __shared__ float xsq_s[BM];
    __shared__ float csq_s[BN];

    const int t  = threadIdx.x;
    const int bm = blockIdx.y;
    const int bn = blockIdx.x;

    if (t < BM) { xsq_s[t] = 0.f; csq_s[t] = 0.f; }

    // Cooperative load mapping: per tile, 128 rows x 8 float4.
    // thread t owns col4 = t&7 and rows {32p + (t>>3)} for p=0..3 (fixed all iters).
    const int lr = t >> 3;
    const int c4 = t & 7;

    const float4* gA = reinterpret_cast<const float4*>(X + (size_t)(bm * BM) * DD);
    const float4* gB = reinterpret_cast<const float4*>(C + (size_t)(bn * BN) * DD);
    const int row4 = DD / 4;  // 768 float4 per row

    float4 ra[4], rb[4];
    float xs[4] = {0.f, 0.f, 0.f, 0.f};
    float cs[4] = {0.f, 0.f, 0.f, 0.f};

    auto ldg_tiles = [&](int kt) {
        const int k4 = kt * (BK / 4);
        #pragma unroll
        for (int p = 0; p < 4; p++) {
            const int row = p * 32 + lr;
            ra[p] = gA[(size_t)row * row4 + k4 + c4];
            rb[p] = gB[(size_t)row * row4 + k4 + c4];
        }
    };

    auto sts_tiles = [&](int buf) {
        #pragma unroll
        for (int p = 0; p < 4; p++) {
            const int row = p * 32 + lr;
            float4 v = ra[p];
            xs[p] += v.x * v.x + v.y * v.y + v.z * v.z + v.w * v.w;
            __nv_bfloat162 lo = __float22bfloat162_rn(make_float2(v.x, v.y));
            __nv_bfloat162 hi = __float22bfloat162_rn(make_float2(v.z, v.w));
            uint2 u;
            u.x = *reinterpret_cast<uint32_t*>(&lo);
            u.y = *reinterpret_cast<uint32_t*>(&hi);
            *reinterpret_cast<uint2*>(&As[buf][row][c4 * 4]) = u;

            v = rb[p];
            cs[p] += v.x * v.x + v.y * v.y + v.z * v.z + v.w * v.w;
            lo = __float22bfloat162_rn(make_float2(v.x, v.y));
            hi = __float22bfloat162_rn(make_float2(v.z, v.w));
            u.x = *reinterpret_cast<uint32_t*>(&lo);
            u.y = *reinterpret_cast<uint32_t*>(&hi);
            *reinterpret_cast<uint2*>(&Bs[buf][row][c4 * 4]) = u;
        }
    };

    // Warp tiling: 4 warps in M (32 rows each), 2 in N (64 cols each).
    const int warp = t >> 5;
    const int lane = t & 31;
    const int wm = warp & 3;
    const int wn = warp >> 2;
    const int fr = lane >> 2;        // fragment row 0..7
    const int fc = (lane & 3) * 2;   // fragment k base

    float acc[2][8][4];
    #pragma unroll
    for (int i = 0; i < 2; i++)
        #pragma unroll
        for (int j = 0; j < 8; j++)
            #pragma unroll
            for (int q = 0; q < 4; q++) acc[i][j][q] = 0.f;

    ldg_tiles(0);
    sts_tiles(0);
    __syncthreads();

    for (int kt = 0; kt < NT; kt++) {
        const int buf = kt & 1;
        if (kt + 1 < NT) ldg_tiles(kt + 1);

        #pragma unroll
        for (int ks = 0; ks < 2; ks++) {
            const int kof = ks * 16;
            uint32_t bfrag[8][2];
            #pragma unroll
            for (int j = 0; j < 8; j++) {
                const __nv_bfloat16* bp = &Bs[buf][wn * 64 + j * 8 + fr][kof + fc];
                bfrag[j][0] = *reinterpret_cast<const uint32_t*>(bp);
                bfrag[j][1] = *reinterpret_cast<const uint32_t*>(bp + 8);
            }
            #pragma unroll
            for (int i = 0; i < 2; i++) {
                const __nv_bfloat16* ap = &As[buf][wm * 32 + i * 16 + fr][kof + fc];
                uint32_t a0 = *reinterpret_cast<const uint32_t*>(ap);
                uint32_t a1 = *reinterpret_cast<const uint32_t*>(ap + 8 * LDS_STRIDE);
                uint32_t a2 = *reinterpret_cast<const uint32_t*>(ap + 8);
                uint32_t a3 = *reinterpret_cast<const uint32_t*>(ap + 8 * LDS_STRIDE + 8);
                #pragma unroll
                for (int j = 0; j < 8; j++) {
                    asm volatile(
                        "mma.sync.aligned.m16n8k16.row.col.f32.bf16.bf16.f32 "
                        "{%0,%1,%2,%3}, {%4,%5,%6,%7}, {%8,%9}, {%0,%1,%2,%3};\n"
                        : "+f"(acc[i][j][0]), "+f"(acc[i][j][1]),
                          "+f"(acc[i][j][2]), "+f"(acc[i][j][3])
                        : "r"(a0), "r"(a1), "r"(a2), "r"(a3),
                          "r"(bfrag[j][0]), "r"(bfrag[j][1]));
                }
            }
        }

        if (kt + 1 < NT) {
            sts_tiles((kt + 1) & 1);
            __syncthreads();
        }
    }

    // Reduce fp32 norms into shared (each thread owns 4 fixed rows; 8-way contention max).
    #pragma unroll
    for (int p = 0; p < 4; p++) {
        atomicAdd(&xsq_s[p * 32 + lr], xs[p]);
        atomicAdd(&csq_s[p * 32 + lr], cs[p]);
    }
    __syncthreads();

    // Epilogue: dist = sqrt(max(xsq + csq - 2*cross, EPS))
    #pragma unroll
    for (int i = 0; i < 2; i++) {
        const int row_l0 = wm * 32 + i * 16 + fr;
        #pragma unroll
        for (int half = 0; half < 2; half++) {
            const int row_l = row_l0 + half * 8;
            const float xq = xsq_s[row_l];
            const size_t grow = (size_t)bm * BM + row_l;
            #pragma unroll
            for (int j = 0; j < 8; j++) {
                const int col_l = wn * 64 + j * 8 + fc;
                const float cq0 = csq_s[col_l];
                const float cq1 = csq_s[col_l + 1];
                const float cr0 = acc[i][j][half * 2 + 0];
                const float cr1 = acc[i][j][half * 2 + 1];
                const float d0 = sqrtf(fmaxf(xq + cq0 - 2.f * cr0, EPS_F));
                const float d1 = sqrtf(fmaxf(xq + cq1 - 2.f * cr1, EPS_F));
                const int gcol = bn * BN + col_l;
                *reinterpret_cast<float2*>(&out[grow * KK + gcol]) = make_float2(d0, d1);
            }
        }
    }
}

extern "C" void kernel_launch(void* const* d_in, const int* in_sizes, int n_in,
                              void* d_out, int out_size)
{
    const float* X = (const float*)d_in[0];   // inputs  [8192, 3072] fp32
    const float* C = (const float*)d_in[1];   // centers [256, 3072]  fp32
    float* out = (float*)d_out;               // [8192, 256] fp32

    dim3 grid(KK / BN, BB / BM);              // (2, 64) = 128 CTAs
    rbf_dist_kernel<<<grid, 256>>>(X, C, out);
}